// round 7
// baseline (speedup 1.0000x reference)
#include <cuda_runtime.h>
#include <math.h>
#include <stdint.h>

#define EMB   1024
#define HS    64
#define TSEQ  4096
#define BATCH 4
#define MTOT  (BATCH * TSEQ)   // 16384 rows

#define NQT    64              // 64-row q tiles per batch
#define CHUNK  16              // kv-tiles per partial block
#define NBLK   160             // sum_{c=0..3} (64-16c) blocks per batch

// Scratch (device globals: allocation-free rule)
__device__ float g_q[MTOT * HS];
__device__ float g_k[MTOT * HS];
__device__ float g_v[MTOT * HS];
__device__ float g_po[BATCH * NBLK * 64 * HS];   // partial O (unnormalized)
__device__ float g_pm[BATCH * NBLK * 64];        // partial row max
__device__ float g_pl[BATCH * NBLK * 64];        // partial row sum

// ---- packed fp32x2 ops (Blackwell FFMA2 path; exact fp32 per lane) ----
#define FMA2(d, a, b) \
    asm("fma.rn.f32x2 %0, %1, %2, %0;" : "+l"(d) : "l"(a), "l"(b))
#define MUL2(d, a) \
    asm("mul.rn.f32x2 %0, %0, %1;" : "+l"(d) : "l"(a))
#define PACK2(d, x) \
    asm("mov.b64 %0, {%1, %1};" : "=l"(d) : "r"(__float_as_uint(x)))
#define UNPACK2(x, y, d) do { \
    unsigned _lo, _hi; \
    asm("mov.b64 {%0, %1}, %2;" : "=r"(_lo), "=r"(_hi) : "l"(d)); \
    (x) = __uint_as_float(_lo); (y) = __uint_as_float(_hi); } while (0)

// ---------------------------------------------------------------------------
// Kernel 1: fused QKV projection.  [q|k|v] = X @ [Wq|Wk|Wv].
// BM=64 rows, BN=3x64 cols, BK=32. 256 threads (2 blocks/SM -> one full
// wave at grid=256); each thread owns 4 rows x (3 x 4 cols).
// X tile stored as DUPLICATED u64 pairs (v,v): a-operand is one broadcast
// LDS.64 straight into fma.rn.f32x2 -- no pack movs in the hot loop.
// ---------------------------------------------------------------------------
#define XDS 33   // u64 stride of X-dup tile rows
#define WST 68   // float stride of W tile rows

__global__ __launch_bounds__(256, 2) void qkv_kernel(
    const float* __restrict__ X,
    const float* __restrict__ Wq,
    const float* __restrict__ Wk,
    const float* __restrict__ Wv)
{
    __shared__ __align__(16) unsigned long long Xd[64 * XDS];  // dup pairs
    __shared__ __align__(16) float Ws[3][32 * WST];

    const int tid = threadIdx.x;
    const int tx = tid & 15;        // col group per W: cols 4*tx..4*tx+3
    const int ty = tid >> 4;        // 0..15 -> rows 4*ty..4*ty+3
    const int m0 = blockIdx.x * 64;

    unsigned long long acc[3][4][2];
#pragma unroll
    for (int w = 0; w < 3; w++)
#pragma unroll
        for (int i = 0; i < 4; i++) { acc[w][i][0] = 0ull; acc[w][i][1] = 0ull; }

    for (int k0 = 0; k0 < EMB; k0 += 32) {
        // X tile 64x32 -> dup u64 (coalesced 128B global reads)
#pragma unroll
        for (int t = 0; t < 2; t++) {
            int idx = tid + 256 * t;      // 0..511
            int row = idx >> 3;           // 0..63
            int cg  = idx & 7;            // 0..7
            float4 xv = *(const float4*)&X[(size_t)(m0 + row) * EMB + k0 + 4 * cg];
            unsigned long long d;
            PACK2(d, xv.x); Xd[row * XDS + 4 * cg + 0] = d;
            PACK2(d, xv.y); Xd[row * XDS + 4 * cg + 1] = d;
            PACK2(d, xv.z); Xd[row * XDS + 4 * cg + 2] = d;
            PACK2(d, xv.w); Xd[row * XDS + 4 * cg + 3] = d;
        }
        // W tiles 32x64 each
#pragma unroll
        for (int t = 0; t < 2; t++) {
            int idx = tid + 256 * t;      // 0..511
            int wr = idx >> 4;            // 0..31
            int cg = idx & 15;            // 0..15
            *(float4*)&Ws[0][wr * WST + 4 * cg] =
                *(const float4*)&Wq[(size_t)(k0 + wr) * HS + 4 * cg];
            *(float4*)&Ws[1][wr * WST + 4 * cg] =
                *(const float4*)&Wk[(size_t)(k0 + wr) * HS + 4 * cg];
            *(float4*)&Ws[2][wr * WST + 4 * cg] =
                *(const float4*)&Wv[(size_t)(k0 + wr) * HS + 4 * cg];
        }
        __syncthreads();

#pragma unroll 8
        for (int kk = 0; kk < 32; kk++) {
            unsigned long long a0 = Xd[(4 * ty + 0) * XDS + kk];
            unsigned long long a1 = Xd[(4 * ty + 1) * XDS + kk];
            unsigned long long a2 = Xd[(4 * ty + 2) * XDS + kk];
            unsigned long long a3 = Xd[(4 * ty + 3) * XDS + kk];
            ulonglong2 b0 = *(const ulonglong2*)&Ws[0][kk * WST + 4 * tx];
            ulonglong2 b1 = *(const ulonglong2*)&Ws[1][kk * WST + 4 * tx];
            ulonglong2 b2 = *(const ulonglong2*)&Ws[2][kk * WST + 4 * tx];
            FMA2(acc[0][0][0], a0, b0.x); FMA2(acc[0][0][1], a0, b0.y);
            FMA2(acc[0][1][0], a1, b0.x); FMA2(acc[0][1][1], a1, b0.y);
            FMA2(acc[0][2][0], a2, b0.x); FMA2(acc[0][2][1], a2, b0.y);
            FMA2(acc[0][3][0], a3, b0.x); FMA2(acc[0][3][1], a3, b0.y);
            FMA2(acc[1][0][0], a0, b1.x); FMA2(acc[1][0][1], a0, b1.y);
            FMA2(acc[1][1][0], a1, b1.x); FMA2(acc[1][1][1], a1, b1.y);
            FMA2(acc[1][2][0], a2, b1.x); FMA2(acc[1][2][1], a2, b1.y);
            FMA2(acc[1][3][0], a3, b1.x); FMA2(acc[1][3][1], a3, b1.y);
            FMA2(acc[2][0][0], a0, b2.x); FMA2(acc[2][0][1], a0, b2.y);
            FMA2(acc[2][1][0], a1, b2.x); FMA2(acc[2][1][1], a1, b2.y);
            FMA2(acc[2][2][0], a2, b2.x); FMA2(acc[2][2][1], a2, b2.y);
            FMA2(acc[2][3][0], a3, b2.x); FMA2(acc[2][3][1], a3, b2.y);
        }
        __syncthreads();
    }

#pragma unroll
    for (int i = 0; i < 4; i++) {
        size_t row = (size_t)(m0 + 4 * ty + i);
        *(ulonglong2*)&g_q[row * HS + 4 * tx] = make_ulonglong2(acc[0][i][0], acc[0][i][1]);
        *(ulonglong2*)&g_k[row * HS + 4 * tx] = make_ulonglong2(acc[1][i][0], acc[1][i][1]);
        *(ulonglong2*)&g_v[row * HS + 4 * tx] = make_ulonglong2(acc[2][i][0], acc[2][i][1]);
    }
}

// ---------------------------------------------------------------------------
// Kernel 2: split-KV flash attention partials, packed f32x2 math.
// Q and P tiles in smem as DUPLICATED u64 pairs -> broadcast LDS.64
// a-operands, zero pack movs in the two GEMM loops.
// 2 blocks/SM (launch_bounds), 99KB dynamic smem per block.
// Block map (per batch): chunk c in 0..3, base(c)=64c-8c(c-1), qt=63-idx.
// ---------------------------------------------------------------------------
#define QDS 66   // u64 stride for Qd/Pd rows (528B, 16B-aligned)
#define VST 68   // float stride for Vs
#define ATTN_SMEM_BYTES (2 * 64 * QDS * 8 + 64 * 64 * 4 + 64 * VST * 4)

__global__ __launch_bounds__(256, 2) void attn_partial_kernel(void)
{
    extern __shared__ __align__(16) char smbase[];
    unsigned long long* Qd = (unsigned long long*)smbase;            // [64][66] dup
    unsigned long long* Pd = Qd + 64 * QDS;                          // [64][66] dup
    float* Kst = (float*)(Pd + 64 * QDS);                            // [64][64] transposed
    float* Vs  = Kst + 64 * 64;                                      // [64][68] natural

    const int b = blockIdx.y;
    const int l = blockIdx.x;

    int c, idx;
    if      (l < 64)  { c = 0; idx = l; }
    else if (l < 112) { c = 1; idx = l - 64; }
    else if (l < 144) { c = 2; idx = l - 112; }
    else              { c = 3; idx = l - 144; }
    const int qt  = 63 - idx;              // descending size (LPT)
    const int kt0 = 16 * c;
    const int kt1 = min(16 * c + CHUNK, qt + 1);

    const int tid = threadIdx.x;
    const int tx = tid & 15;
    const int ty = tid >> 4;

    const float* Qg = g_q + ((size_t)b * TSEQ + qt * 64) * HS;
    const float* Kg = g_k + (size_t)b * TSEQ * HS;
    const float* Vg = g_v + (size_t)b * TSEQ * HS;

    // ---- load Q tile once (dup-packed) ----
    {
        int r  = tid & 63;
        int cb = tid >> 6;
#pragma unroll
        for (int t = 0; t < 4; t++) {
            int c4 = cb + 4 * t;
            float4 v = *(const float4*)&Qg[(size_t)r * HS + 4 * c4];
            unsigned long long d;
            PACK2(d, v.x); Qd[r * QDS + 4 * c4 + 0] = d;
            PACK2(d, v.y); Qd[r * QDS + 4 * c4 + 1] = d;
            PACK2(d, v.z); Qd[r * QDS + 4 * c4 + 2] = d;
            PACK2(d, v.w); Qd[r * QDS + 4 * c4 + 3] = d;
        }
    }

    float m_[4], l_[4];
    unsigned long long o2[4][2];
#pragma unroll
    for (int i = 0; i < 4; i++) {
        m_[i] = -1e30f; l_[i] = 0.0f;
        o2[i][0] = 0ull; o2[i][1] = 0ull;
    }

    for (int kt = kt0; kt < kt1; kt++) {
        const float* Kt = Kg + (size_t)kt * 64 * HS;
        const float* Vt = Vg + (size_t)kt * 64 * HS;

        // ---- load K (transposed) and V (natural) tiles ----
        {
            int r  = tid & 63;
            int cb = tid >> 6;
#pragma unroll
            for (int t = 0; t < 4; t++) {
                int c4 = cb + 4 * t;
                float4 kv = *(const float4*)&Kt[(size_t)r * HS + 4 * c4];
                Kst[(4 * c4 + 0) * 64 + r] = kv.x;
                Kst[(4 * c4 + 1) * 64 + r] = kv.y;
                Kst[(4 * c4 + 2) * 64 + r] = kv.z;
                Kst[(4 * c4 + 3) * 64 + r] = kv.w;
                float4 vv = *(const float4*)&Vt[(size_t)r * HS + 4 * c4];
                *(float4*)&Vs[r * VST + 4 * c4] = vv;
            }
        }
        __syncthreads();

        // ---- S = Q @ K^T: 4 LDS.64 + 1 LDS.128 + 8 FFMA2 per h ----
        unsigned long long s2[4][2];
#pragma unroll
        for (int i = 0; i < 4; i++) { s2[i][0] = 0ull; s2[i][1] = 0ull; }

#pragma unroll 8
        for (int h = 0; h < 64; h++) {
            ulonglong2 bb = *(const ulonglong2*)&Kst[h * 64 + 4 * tx];
            unsigned long long a0 = Qd[(4 * ty + 0) * QDS + h];
            unsigned long long a1 = Qd[(4 * ty + 1) * QDS + h];
            unsigned long long a2 = Qd[(4 * ty + 2) * QDS + h];
            unsigned long long a3 = Qd[(4 * ty + 3) * QDS + h];
            FMA2(s2[0][0], a0, bb.x); FMA2(s2[0][1], a0, bb.y);
            FMA2(s2[1][0], a1, bb.x); FMA2(s2[1][1], a1, bb.y);
            FMA2(s2[2][0], a2, bb.x); FMA2(s2[2][1], a2, bb.y);
            FMA2(s2[3][0], a3, bb.x); FMA2(s2[3][1], a3, bb.y);
        }

        float s[4][4];
#pragma unroll
        for (int i = 0; i < 4; i++) {
            UNPACK2(s[i][0], s[i][1], s2[i][0]);
            UNPACK2(s[i][2], s[i][3], s2[i][1]);
        }

        // ---- causal mask on the diagonal tile ----
        if (kt == qt) {
#pragma unroll
            for (int i = 0; i < 4; i++)
#pragma unroll
                for (int j = 0; j < 4; j++)
                    if (4 * tx + j > 4 * ty + i) s[i][j] = -1e30f;
        }

        // ---- online softmax (rows reduced across 16 tx lanes) ----
#pragma unroll
        for (int i = 0; i < 4; i++) {
            float mx = fmaxf(fmaxf(s[i][0], s[i][1]), fmaxf(s[i][2], s[i][3]));
#pragma unroll
            for (int off = 1; off < 16; off <<= 1)
                mx = fmaxf(mx, __shfl_xor_sync(0xffffffffu, mx, off));
            float mnew = fmaxf(m_[i], mx);
            float alpha = __expf(m_[i] - mnew);
            m_[i] = mnew;
            float ps = 0.0f;
#pragma unroll
            for (int j = 0; j < 4; j++) {
                s[i][j] = __expf(s[i][j] - mnew);
                ps += s[i][j];
            }
#pragma unroll
            for (int off = 1; off < 16; off <<= 1)
                ps += __shfl_xor_sync(0xffffffffu, ps, off);
            l_[i] = l_[i] * alpha + ps;
            unsigned long long al2;
            PACK2(al2, alpha);
            MUL2(o2[i][0], al2);
            MUL2(o2[i][1], al2);
        }

        // ---- publish P tile (dup-packed) ----
#pragma unroll
        for (int i = 0; i < 4; i++) {
            unsigned long long d0, d1, d2, d3;
            PACK2(d0, s[i][0]); PACK2(d1, s[i][1]);
            PACK2(d2, s[i][2]); PACK2(d3, s[i][3]);
            unsigned long long* p = &Pd[(4 * ty + i) * QDS + 4 * tx];
            *(ulonglong2*)(p + 0) = make_ulonglong2(d0, d1);
            *(ulonglong2*)(p + 2) = make_ulonglong2(d2, d3);
        }
        __syncthreads();

        // ---- O += P @ V: 4 LDS.64 + 1 LDS.128 + 8 FFMA2 per j ----
#pragma unroll 8
        for (int j = 0; j < 64; j++) {
            ulonglong2 vv = *(const ulonglong2*)&Vs[j * VST + 4 * tx];
            unsigned long long p0 = Pd[(4 * ty + 0) * QDS + j];
            unsigned long long p1 = Pd[(4 * ty + 1) * QDS + j];
            unsigned long long p2 = Pd[(4 * ty + 2) * QDS + j];
            unsigned long long p3 = Pd[(4 * ty + 3) * QDS + j];
            FMA2(o2[0][0], p0, vv.x); FMA2(o2[0][1], p0, vv.y);
            FMA2(o2[1][0], p1, vv.x); FMA2(o2[1][1], p1, vv.y);
            FMA2(o2[2][0], p2, vv.x); FMA2(o2[2][1], p2, vv.y);
            FMA2(o2[3][0], p3, vv.x); FMA2(o2[3][1], p3, vv.y);
        }
        __syncthreads();
    }

    // ---- write partial (unnormalized O, row max m, row sum l) ----
    const size_t slot = (size_t)b * NBLK + l;
    float* PO = g_po + slot * 64 * HS;
#pragma unroll
    for (int i = 0; i < 4; i++)
        *(ulonglong2*)&PO[(size_t)(4 * ty + i) * HS + 4 * tx] =
            make_ulonglong2(o2[i][0], o2[i][1]);
    if (tx == 0) {
#pragma unroll
        for (int i = 0; i < 4; i++) {
            g_pm[slot * 64 + 4 * ty + i] = m_[i];
            g_pl[slot * 64 + 4 * ty + i] = l_[i];
        }
    }
}

// ---------------------------------------------------------------------------
// Kernel 3: combine partials (log-sum-exp merge) + epilogue /(l*8).
// slot for (qt, c): base(c) + (63 - qt), base(c) = 64c - 8c(c-1).
// ---------------------------------------------------------------------------
__global__ __launch_bounds__(256) void attn_reduce_kernel(float* __restrict__ out)
{
    const int b  = blockIdx.y;
    const int qt = blockIdx.x;
    const int tid = threadIdx.x;
    const int r  = tid >> 2;
    const int cg = (tid & 3) * 16;

    const int nch = qt / CHUNK + 1;

    float m = -1e30f;
    for (int c = 0; c < nch; c++) {
        int base = 64 * c - 8 * c * (c - 1);
        size_t slot = (size_t)b * NBLK + base + (63 - qt);
        m = fmaxf(m, g_pm[slot * 64 + r]);
    }

    float lsum = 0.0f;
    float acc[16];
#pragma unroll
    for (int t = 0; t < 16; t++) acc[t] = 0.0f;

    for (int c = 0; c < nch; c++) {
        int base = 64 * c - 8 * c * (c - 1);
        size_t slot = (size_t)b * NBLK + base + (63 - qt);
        float w = __expf(g_pm[slot * 64 + r] - m);
        lsum = fmaf(w, g_pl[slot * 64 + r], lsum);
        const float* PO = g_po + (slot * 64 + r) * HS + cg;
#pragma unroll
        for (int t = 0; t < 4; t++) {
            float4 v = *(const float4*)&PO[4 * t];
            acc[4 * t + 0] = fmaf(w, v.x, acc[4 * t + 0]);
            acc[4 * t + 1] = fmaf(w, v.y, acc[4 * t + 1]);
            acc[4 * t + 2] = fmaf(w, v.z, acc[4 * t + 2]);
            acc[4 * t + 3] = fmaf(w, v.w, acc[4 * t + 3]);
        }
    }

    // /(l) for softmax, /8 for the reference's post-softmax /sqrt(HS) quirk
    const float inv = 1.0f / (lsum * 8.0f);
    float* O = out + ((size_t)b * TSEQ + qt * 64 + r) * HS + cg;
#pragma unroll
    for (int t = 0; t < 4; t++) {
        float4 v = make_float4(acc[4 * t + 0] * inv, acc[4 * t + 1] * inv,
                               acc[4 * t + 2] * inv, acc[4 * t + 3] * inv);
        *(float4*)&O[4 * t] = v;
    }
}

// ---------------------------------------------------------------------------
extern "C" void kernel_launch(void* const* d_in, const int* in_sizes, int n_in,
                              void* d_out, int out_size)
{
    const float* X  = (const float*)d_in[0];
    const float* Wq = (const float*)d_in[1];
    const float* Wk = (const float*)d_in[2];
    const float* Wv = (const float*)d_in[3];
    float* out = (float*)d_out;

    (void)in_sizes; (void)n_in; (void)out_size;

    // Fused QKV projection: 256 blocks x 256 threads (one full wave @ 2/SM)
    qkv_kernel<<<MTOT / 64, 256>>>(X, Wq, Wk, Wv);

    // Flash attention partials: (160 chunk-blocks, 4 batches)
    cudaFuncSetAttribute(attn_partial_kernel,
                         cudaFuncAttributeMaxDynamicSharedMemorySize, ATTN_SMEM_BYTES);
    dim3 g2(NBLK, BATCH);
    attn_partial_kernel<<<g2, 256, ATTN_SMEM_BYTES>>>();

    // Combine partials + epilogue
    dim3 g3(NQT, BATCH);
    attn_reduce_kernel<<<g3, 256>>>(out);
}

// round 8
// speedup vs baseline: 1.1058x; 1.1058x over previous
#include <cuda_runtime.h>
#include <math.h>
#include <stdint.h>

#define EMB   1024
#define HS    64
#define TSEQ  4096
#define BATCH 4
#define MTOT  (BATCH * TSEQ)   // 16384 rows

#define NQT    64              // 64-row q tiles per batch
#define CHUNK  16              // kv-tiles per partial block
#define NBLK   160             // sum_{c=0..3} (64-16c) blocks per batch

// Scratch (device globals: allocation-free rule)
__device__ float g_q[MTOT * HS];
__device__ float g_k[MTOT * HS];
__device__ float g_v[MTOT * HS];
__device__ float g_po[BATCH * NBLK * 64 * HS];   // partial O (unnormalized)
__device__ float g_pm[BATCH * NBLK * 64];        // partial row max
__device__ float g_pl[BATCH * NBLK * 64];        // partial row sum

// ---- packed fp32x2 ops (Blackwell FFMA2 path; exact fp32 per lane) ----
#define FMA2(d, a, b) \
    asm("fma.rn.f32x2 %0, %1, %2, %0;" : "+l"(d) : "l"(a), "l"(b))
#define MUL2(d, a) \
    asm("mul.rn.f32x2 %0, %0, %1;" : "+l"(d) : "l"(a))
#define PACK2(d, x) \
    asm("mov.b64 %0, {%1, %1};" : "=l"(d) : "r"(__float_as_uint(x)))
#define UNPACK2(x, y, d) do { \
    unsigned _lo, _hi; \
    asm("mov.b64 {%0, %1}, %2;" : "=r"(_lo), "=r"(_hi) : "l"(d)); \
    (x) = __uint_as_float(_lo); (y) = __uint_as_float(_hi); } while (0)

// ---------------------------------------------------------------------------
// Kernel 1: QKV projection, one W per blockIdx.y.  Y = X @ W.
// BM=64 rows, BN=64 cols, BK=32. 128 threads; 4 rows x 8 cols per thread,
// cols split {4tx..4tx+3, 32+4tx..32+4tx+3} so each b LDS.128 is a
// contiguous 128B warp access (bank-conflict-free, 1 crossbar cyc).
// Crossbar:FMA per warp-kk = 6:8 -> FMA-bound.
// ---------------------------------------------------------------------------
#define XDS 33   // u64 stride of X-dup rows
#define WST 68   // float stride of W rows

__global__ __launch_bounds__(128) void qkv_kernel(
    const float* __restrict__ X,
    const float* __restrict__ Wq,
    const float* __restrict__ Wk,
    const float* __restrict__ Wv)
{
    __shared__ __align__(16) unsigned long long Xd[64 * XDS];  // dup pairs
    __shared__ __align__(16) float Ws[32 * WST];

    const float* W;
    float* Y;
    if (blockIdx.y == 0)      { W = Wq; Y = g_q; }
    else if (blockIdx.y == 1) { W = Wk; Y = g_k; }
    else                      { W = Wv; Y = g_v; }

    const int tid = threadIdx.x;
    const int tx = tid & 7;          // col groups 4tx and 32+4tx
    const int ty = tid >> 3;         // 0..15 -> rows 4*ty..4*ty+3
    const int m0 = blockIdx.x * 64;

    unsigned long long acc[4][4];
#pragma unroll
    for (int i = 0; i < 4; i++)
#pragma unroll
        for (int j = 0; j < 4; j++) acc[i][j] = 0ull;

    for (int k0 = 0; k0 < EMB; k0 += 32) {
        // X tile 64x32 -> dup u64 (coalesced 128B global reads)
#pragma unroll
        for (int t = 0; t < 4; t++) {
            int idx = tid + 128 * t;      // 0..511
            int row = idx >> 3;           // 0..63
            int cg  = idx & 7;            // 0..7
            float4 xv = *(const float4*)&X[(size_t)(m0 + row) * EMB + k0 + 4 * cg];
            unsigned long long d;
            PACK2(d, xv.x); Xd[row * XDS + 4 * cg + 0] = d;
            PACK2(d, xv.y); Xd[row * XDS + 4 * cg + 1] = d;
            PACK2(d, xv.z); Xd[row * XDS + 4 * cg + 2] = d;
            PACK2(d, xv.w); Xd[row * XDS + 4 * cg + 3] = d;
        }
        // W tile 32x64
#pragma unroll
        for (int t = 0; t < 4; t++) {
            int idx = tid + 128 * t;      // 0..511
            int wr = idx >> 4;            // 0..31
            int cg = idx & 15;            // 0..15
            *(float4*)&Ws[wr * WST + 4 * cg] =
                *(const float4*)&W[(size_t)(k0 + wr) * HS + 4 * cg];
        }
        __syncthreads();

#pragma unroll 8
        for (int kk = 0; kk < 32; kk++) {
            unsigned long long a0 = Xd[(4 * ty + 0) * XDS + kk];
            unsigned long long a1 = Xd[(4 * ty + 1) * XDS + kk];
            unsigned long long a2 = Xd[(4 * ty + 2) * XDS + kk];
            unsigned long long a3 = Xd[(4 * ty + 3) * XDS + kk];
            ulonglong2 bL = *(const ulonglong2*)&Ws[kk * WST + 4 * tx];
            ulonglong2 bH = *(const ulonglong2*)&Ws[kk * WST + 32 + 4 * tx];
            FMA2(acc[0][0], a0, bL.x); FMA2(acc[0][1], a0, bL.y);
            FMA2(acc[0][2], a0, bH.x); FMA2(acc[0][3], a0, bH.y);
            FMA2(acc[1][0], a1, bL.x); FMA2(acc[1][1], a1, bL.y);
            FMA2(acc[1][2], a1, bH.x); FMA2(acc[1][3], a1, bH.y);
            FMA2(acc[2][0], a2, bL.x); FMA2(acc[2][1], a2, bL.y);
            FMA2(acc[2][2], a2, bH.x); FMA2(acc[2][3], a2, bH.y);
            FMA2(acc[3][0], a3, bL.x); FMA2(acc[3][1], a3, bL.y);
            FMA2(acc[3][2], a3, bH.x); FMA2(acc[3][3], a3, bH.y);
        }
        __syncthreads();
    }

#pragma unroll
    for (int i = 0; i < 4; i++) {
        size_t row = (size_t)(m0 + 4 * ty + i);
        *(ulonglong2*)&Y[row * HS + 4 * tx]      = make_ulonglong2(acc[i][0], acc[i][1]);
        *(ulonglong2*)&Y[row * HS + 32 + 4 * tx] = make_ulonglong2(acc[i][2], acc[i][3]);
    }
}

// ---------------------------------------------------------------------------
// Kernel 2: split-KV flash attention partials, packed f32x2 math.
// 128 threads, 4 rows x 8 split cols per thread; Q/P dup-packed in smem,
// K transposed / V natural read as contiguous-128B LDS.128 pairs.
// 2 blocks/SM (101KB smem each). Grid flattened: x = 4*l + b (global LPT).
// Job map (per batch): chunk c in 0..3, base(c)=64c-8c(c-1), qt=63-idx.
// ---------------------------------------------------------------------------
#define QDS 66   // u64 stride for Qd/Pd rows
#define VST 68   // float stride for Vs
#define ATTN_SMEM_BYTES (2 * 64 * QDS * 8 + 64 * 64 * 4 + 64 * VST * 4)

__global__ __launch_bounds__(128, 2) void attn_partial_kernel(void)
{
    extern __shared__ __align__(16) char smbase[];
    unsigned long long* Qd = (unsigned long long*)smbase;   // [64][QDS] dup
    unsigned long long* Pd = Qd + 64 * QDS;                 // [64][QDS] dup
    float* Kst = (float*)(Pd + 64 * QDS);                   // [64][64] transposed
    float* Vs  = Kst + 64 * 64;                             // [64][VST] natural

    const int b = blockIdx.x & 3;
    const int l = blockIdx.x >> 2;

    int c, idx;
    if      (l < 64)  { c = 0; idx = l; }
    else if (l < 112) { c = 1; idx = l - 64; }
    else if (l < 144) { c = 2; idx = l - 112; }
    else              { c = 3; idx = l - 144; }
    const int qt  = 63 - idx;              // descending size (LPT)
    const int kt0 = 16 * c;
    const int kt1 = min(16 * c + CHUNK, qt + 1);

    const int tid = threadIdx.x;
    const int tx = tid & 7;
    const int ty = tid >> 3;               // 0..15

    const float* Qg = g_q + ((size_t)b * TSEQ + qt * 64) * HS;
    const float* Kg = g_k + (size_t)b * TSEQ * HS;
    const float* Vg = g_v + (size_t)b * TSEQ * HS;

    // ---- load Q tile once (dup-packed) ----
    {
        int r  = tid & 63;
        int cb = tid >> 6;                 // 0..1
#pragma unroll
        for (int t = 0; t < 8; t++) {
            int c4 = cb + 2 * t;           // 0..15
            float4 v = *(const float4*)&Qg[(size_t)r * HS + 4 * c4];
            unsigned long long d;
            PACK2(d, v.x); Qd[r * QDS + 4 * c4 + 0] = d;
            PACK2(d, v.y); Qd[r * QDS + 4 * c4 + 1] = d;
            PACK2(d, v.z); Qd[r * QDS + 4 * c4 + 2] = d;
            PACK2(d, v.w); Qd[r * QDS + 4 * c4 + 3] = d;
        }
    }

    float m_[4], l_[4];
    unsigned long long o2[4][4];
#pragma unroll
    for (int i = 0; i < 4; i++) {
        m_[i] = -1e30f; l_[i] = 0.0f;
#pragma unroll
        for (int j = 0; j < 4; j++) o2[i][j] = 0ull;
    }

    for (int kt = kt0; kt < kt1; kt++) {
        const float* Kt = Kg + (size_t)kt * 64 * HS;
        const float* Vt = Vg + (size_t)kt * 64 * HS;

        // ---- load K (transposed) and V (natural) tiles ----
        {
            int r  = tid & 63;
            int cb = tid >> 6;
#pragma unroll
            for (int t = 0; t < 8; t++) {
                int c4 = cb + 2 * t;
                float4 kv = *(const float4*)&Kt[(size_t)r * HS + 4 * c4];
                Kst[(4 * c4 + 0) * 64 + r] = kv.x;
                Kst[(4 * c4 + 1) * 64 + r] = kv.y;
                Kst[(4 * c4 + 2) * 64 + r] = kv.z;
                Kst[(4 * c4 + 3) * 64 + r] = kv.w;
                float4 vv = *(const float4*)&Vt[(size_t)r * HS + 4 * c4];
                *(float4*)&Vs[r * VST + 4 * c4] = vv;
            }
        }
        __syncthreads();

        // ---- S = Q @ K^T: 4 LDS.64 + 2 contiguous LDS.128 + 16 FFMA2 / h ----
        unsigned long long s2[4][4];
#pragma unroll
        for (int i = 0; i < 4; i++)
#pragma unroll
            for (int j = 0; j < 4; j++) s2[i][j] = 0ull;

#pragma unroll 8
        for (int h = 0; h < 64; h++) {
            ulonglong2 bL = *(const ulonglong2*)&Kst[h * 64 + 4 * tx];
            ulonglong2 bH = *(const ulonglong2*)&Kst[h * 64 + 32 + 4 * tx];
            unsigned long long a0 = Qd[(4 * ty + 0) * QDS + h];
            unsigned long long a1 = Qd[(4 * ty + 1) * QDS + h];
            unsigned long long a2 = Qd[(4 * ty + 2) * QDS + h];
            unsigned long long a3 = Qd[(4 * ty + 3) * QDS + h];
            FMA2(s2[0][0], a0, bL.x); FMA2(s2[0][1], a0, bL.y);
            FMA2(s2[0][2], a0, bH.x); FMA2(s2[0][3], a0, bH.y);
            FMA2(s2[1][0], a1, bL.x); FMA2(s2[1][1], a1, bL.y);
            FMA2(s2[1][2], a1, bH.x); FMA2(s2[1][3], a1, bH.y);
            FMA2(s2[2][0], a2, bL.x); FMA2(s2[2][1], a2, bL.y);
            FMA2(s2[2][2], a2, bH.x); FMA2(s2[2][3], a2, bH.y);
            FMA2(s2[3][0], a3, bL.x); FMA2(s2[3][1], a3, bL.y);
            FMA2(s2[3][2], a3, bH.x); FMA2(s2[3][3], a3, bH.y);
        }

        // s[i][0..3] -> cols 4tx+j ; s[i][4..7] -> cols 32+4tx+(j-4)
        float s[4][8];
#pragma unroll
        for (int i = 0; i < 4; i++) {
            UNPACK2(s[i][0], s[i][1], s2[i][0]);
            UNPACK2(s[i][2], s[i][3], s2[i][1]);
            UNPACK2(s[i][4], s[i][5], s2[i][2]);
            UNPACK2(s[i][6], s[i][7], s2[i][3]);
        }

        // ---- causal mask on the diagonal tile ----
        if (kt == qt) {
#pragma unroll
            for (int i = 0; i < 4; i++) {
                int row = 4 * ty + i;
#pragma unroll
                for (int j = 0; j < 4; j++) {
                    if (4 * tx + j > row)      s[i][j]     = -1e30f;
                    if (32 + 4 * tx + j > row) s[i][j + 4] = -1e30f;
                }
            }
        }

        // ---- online softmax (row spread over 8 tx lanes; xor 1,2,4) ----
#pragma unroll
        for (int i = 0; i < 4; i++) {
            float mx = s[i][0];
#pragma unroll
            for (int j = 1; j < 8; j++) mx = fmaxf(mx, s[i][j]);
#pragma unroll
            for (int off = 1; off < 8; off <<= 1)
                mx = fmaxf(mx, __shfl_xor_sync(0xffffffffu, mx, off));
            float mnew = fmaxf(m_[i], mx);
            float alpha = __expf(m_[i] - mnew);
            m_[i] = mnew;
            float ps = 0.0f;
#pragma unroll
            for (int j = 0; j < 8; j++) {
                s[i][j] = __expf(s[i][j] - mnew);
                ps += s[i][j];
            }
#pragma unroll
            for (int off = 1; off < 8; off <<= 1)
                ps += __shfl_xor_sync(0xffffffffu, ps, off);
            l_[i] = l_[i] * alpha + ps;
            unsigned long long al2;
            PACK2(al2, alpha);
            MUL2(o2[i][0], al2); MUL2(o2[i][1], al2);
            MUL2(o2[i][2], al2); MUL2(o2[i][3], al2);
        }

        // ---- publish P tile (dup-packed, split cols) ----
#pragma unroll
        for (int i = 0; i < 4; i++) {
            unsigned long long d0, d1, d2, d3;
            unsigned long long* p = &Pd[(4 * ty + i) * QDS];
            PACK2(d0, s[i][0]); PACK2(d1, s[i][1]);
            PACK2(d2, s[i][2]); PACK2(d3, s[i][3]);
            *(ulonglong2*)(p + 4 * tx + 0) = make_ulonglong2(d0, d1);
            *(ulonglong2*)(p + 4 * tx + 2) = make_ulonglong2(d2, d3);
            PACK2(d0, s[i][4]); PACK2(d1, s[i][5]);
            PACK2(d2, s[i][6]); PACK2(d3, s[i][7]);
            *(ulonglong2*)(p + 32 + 4 * tx + 0) = make_ulonglong2(d0, d1);
            *(ulonglong2*)(p + 32 + 4 * tx + 2) = make_ulonglong2(d2, d3);
        }
        __syncthreads();

        // ---- O += P @ V: same 6:8 crossbar:FMA shape ----
#pragma unroll 8
        for (int j = 0; j < 64; j++) {
            ulonglong2 vL = *(const ulonglong2*)&Vs[j * VST + 4 * tx];
            ulonglong2 vH = *(const ulonglong2*)&Vs[j * VST + 32 + 4 * tx];
            unsigned long long p0 = Pd[(4 * ty + 0) * QDS + j];
            unsigned long long p1 = Pd[(4 * ty + 1) * QDS + j];
            unsigned long long p2 = Pd[(4 * ty + 2) * QDS + j];
            unsigned long long p3 = Pd[(4 * ty + 3) * QDS + j];
            FMA2(o2[0][0], p0, vL.x); FMA2(o2[0][1], p0, vL.y);
            FMA2(o2[0][2], p0, vH.x); FMA2(o2[0][3], p0, vH.y);
            FMA2(o2[1][0], p1, vL.x); FMA2(o2[1][1], p1, vL.y);
            FMA2(o2[1][2], p1, vH.x); FMA2(o2[1][3], p1, vH.y);
            FMA2(o2[2][0], p2, vL.x); FMA2(o2[2][1], p2, vL.y);
            FMA2(o2[2][2], p2, vH.x); FMA2(o2[2][3], p2, vH.y);
            FMA2(o2[3][0], p3, vL.x); FMA2(o2[3][1], p3, vL.y);
            FMA2(o2[3][2], p3, vH.x); FMA2(o2[3][3], p3, vH.y);
        }
        __syncthreads();
    }

    // ---- write partial (unnormalized O, row max m, row sum l) ----
    const size_t slot = (size_t)b * NBLK + l;
    float* PO = g_po + slot * 64 * HS;
#pragma unroll
    for (int i = 0; i < 4; i++) {
        size_t row = (size_t)(4 * ty + i);
        *(ulonglong2*)&PO[row * HS + 4 * tx]      = make_ulonglong2(o2[i][0], o2[i][1]);
        *(ulonglong2*)&PO[row * HS + 32 + 4 * tx] = make_ulonglong2(o2[i][2], o2[i][3]);
    }
    if (tx == 0) {
#pragma unroll
        for (int i = 0; i < 4; i++) {
            g_pm[slot * 64 + 4 * ty + i] = m_[i];
            g_pl[slot * 64 + 4 * ty + i] = l_[i];
        }
    }
}

// ---------------------------------------------------------------------------
// Kernel 3: combine partials (log-sum-exp merge) + epilogue /(l*8).
// slot for (qt, c): base(c) + (63 - qt), base(c) = 64c - 8c(c-1).
// ---------------------------------------------------------------------------
__global__ __launch_bounds__(256) void attn_reduce_kernel(float* __restrict__ out)
{
    const int b  = blockIdx.y;
    const int qt = blockIdx.x;
    const int tid = threadIdx.x;
    const int r  = tid >> 2;
    const int cg = (tid & 3) * 16;

    const int nch = qt / CHUNK + 1;

    float m = -1e30f;
    for (int c = 0; c < nch; c++) {
        int base = 64 * c - 8 * c * (c - 1);
        size_t slot = (size_t)b * NBLK + base + (63 - qt);
        m = fmaxf(m, g_pm[slot * 64 + r]);
    }

    float lsum = 0.0f;
    float acc[16];
#pragma unroll
    for (int t = 0; t < 16; t++) acc[t] = 0.0f;

    for (int c = 0; c < nch; c++) {
        int base = 64 * c - 8 * c * (c - 1);
        size_t slot = (size_t)b * NBLK + base + (63 - qt);
        float w = __expf(g_pm[slot * 64 + r] - m);
        lsum = fmaf(w, g_pl[slot * 64 + r], lsum);
        const float* PO = g_po + (slot * 64 + r) * HS + cg;
#pragma unroll
        for (int t = 0; t < 4; t++) {
            float4 v = *(const float4*)&PO[4 * t];
            acc[4 * t + 0] = fmaf(w, v.x, acc[4 * t + 0]);
            acc[4 * t + 1] = fmaf(w, v.y, acc[4 * t + 1]);
            acc[4 * t + 2] = fmaf(w, v.z, acc[4 * t + 2]);
            acc[4 * t + 3] = fmaf(w, v.w, acc[4 * t + 3]);
        }
    }

    // /(l) for softmax, /8 for the reference's post-softmax /sqrt(HS) quirk
    const float inv = 1.0f / (lsum * 8.0f);
    float* O = out + ((size_t)b * TSEQ + qt * 64 + r) * HS + cg;
#pragma unroll
    for (int t = 0; t < 4; t++) {
        float4 v = make_float4(acc[4 * t + 0] * inv, acc[4 * t + 1] * inv,
                               acc[4 * t + 2] * inv, acc[4 * t + 3] * inv);
        *(float4*)&O[4 * t] = v;
    }
}

// ---------------------------------------------------------------------------
extern "C" void kernel_launch(void* const* d_in, const int* in_sizes, int n_in,
                              void* d_out, int out_size)
{
    const float* X  = (const float*)d_in[0];
    const float* Wq = (const float*)d_in[1];
    const float* Wk = (const float*)d_in[2];
    const float* Wv = (const float*)d_in[3];
    float* out = (float*)d_out;

    (void)in_sizes; (void)n_in; (void)out_size;

    // QKV projection: (256 row-blocks, 3 weight matrices), 128 threads
    dim3 g1(MTOT / 64, 3);
    qkv_kernel<<<g1, 128>>>(X, Wq, Wk, Wv);

    // Flash attention partials: 640 blocks (batch-interleaved LPT), 128 thr
    cudaFuncSetAttribute(attn_partial_kernel,
                         cudaFuncAttributeMaxDynamicSharedMemorySize, ATTN_SMEM_BYTES);
    attn_partial_kernel<<<NBLK * BATCH, 128, ATTN_SMEM_BYTES>>>();

    // Combine partials + epilogue
    dim3 g3(NQT, BATCH);
    attn_reduce_kernel<<<g3, 256>>>(out);
}